// round 13
// baseline (speedup 1.0000x reference)
#include <cuda_runtime.h>
#include <cuda_bf16.h>
#include <cuda_fp16.h>
#include <cstdint>
#include <cstddef>

#define N_NODES 50000
#define N_EDGES 1600000
#define FEAT    1536
#define FH      768
#define HID     200
#define HB      400
#define NPAD    208

/* ---------------- scratch ---------------- */
__device__ __half g_Hh[(size_t)N_NODES * HB];   /* x @ W1 in fp16 (40 MB) */
__device__ float g_Z  [N_NODES * 4];
__device__ int   g_deg   [N_NODES];
__device__ int   g_off   [N_NODES + 1];
__device__ int   g_cursor[N_NODES];
__device__ uint2 g_edge  [N_EDGES];             /* packed (src, w) */
/* pre-transposed fp16 weights: [branch][n=208][k=768] */
__device__ __half g_Wf[2 * NPAD * FH];

/* ---------------- small PTX helpers ---------------- */
__device__ __forceinline__ uint32_t smem_u32(const void* p) {
    uint32_t a;
    asm("{ .reg .u64 t; cvta.to.shared.u64 t, %1; cvt.u32.u64 %0, t; }"
        : "=r"(a) : "l"(p));
    return a;
}
__device__ __forceinline__ void cp_async16(uint32_t dst, const void* src) {
    asm volatile("cp.async.cg.shared.global [%0], [%1], 16;"
                 :: "r"(dst), "l"(src) : "memory");
}
#define CP_COMMIT() asm volatile("cp.async.commit_group;" ::: "memory")
#define CP_WAIT0()  asm volatile("cp.async.wait_group 0;" ::: "memory")

__device__ __forceinline__ void ldsm_x4(uint32_t a, uint32_t& r0, uint32_t& r1,
                                        uint32_t& r2, uint32_t& r3) {
    asm volatile("ldmatrix.sync.aligned.m8n8.x4.shared.b16 {%0,%1,%2,%3}, [%4];"
                 : "=r"(r0), "=r"(r1), "=r"(r2), "=r"(r3) : "r"(a));
}
__device__ __forceinline__ void ldsm_x2(uint32_t a, uint32_t& r0, uint32_t& r1) {
    asm volatile("ldmatrix.sync.aligned.m8n8.x2.shared.b16 {%0,%1}, [%2];"
                 : "=r"(r0), "=r"(r1) : "r"(a));
}
__device__ __forceinline__ void mma_f16(float* c, const uint32_t* a,
                                        uint32_t b0, uint32_t b1) {
    asm volatile(
        "mma.sync.aligned.m16n8k16.row.col.f32.f16.f16.f32 "
        "{%0,%1,%2,%3}, {%4,%5,%6,%7}, {%8,%9}, {%0,%1,%2,%3};"
        : "+f"(c[0]), "+f"(c[1]), "+f"(c[2]), "+f"(c[3])
        : "r"(a[0]), "r"(a[1]), "r"(a[2]), "r"(a[3]), "r"(b0), "r"(b1));
}

/* ---------------- CSR build ---------------- */
__global__ void k_count(const int* __restrict__ dst) {
    int i = blockIdx.x * blockDim.x + threadIdx.x;
    if (i < N_EDGES) atomicAdd(&g_deg[dst[i]], 1);
}

/* single-block scan: 1024 threads x 49 contiguous elements */
__global__ void __launch_bounds__(1024) k_scan_all() {
    __shared__ int sh[1024];
    const int t = threadIdx.x;
    const int base = t * 49;
    int loc[49];
    int sum = 0;
#pragma unroll
    for (int i = 0; i < 49; ++i) {
        int idx = base + i;
        int v = (idx < N_NODES) ? g_deg[idx] : 0;
        loc[i] = sum;
        sum += v;
    }
    sh[t] = sum;
    __syncthreads();
    for (int s = 1; s < 1024; s <<= 1) {
        int u = (t >= s) ? sh[t - s] : 0;
        __syncthreads();
        sh[t] += u;
        __syncthreads();
    }
    int carry = (t == 0) ? 0 : sh[t - 1];
#pragma unroll
    for (int i = 0; i < 49; ++i) {
        int idx = base + i;
        if (idx < N_NODES) g_off[idx] = carry + loc[i];
    }
    if (t == 1023) g_off[N_NODES] = sh[1023];
}

__global__ void k_fill(const int* __restrict__ src, const int* __restrict__ dst,
                       const float* __restrict__ w) {
    int i = blockIdx.x * blockDim.x + threadIdx.x;
    if (i < N_EDGES) {
        int d = dst[i];
        int p = atomicAdd(&g_cursor[d], 1);
        g_edge[p] = make_uint2((unsigned)src[i], __float_as_uint(w[i]));
    }
}

/* ---------------- weight prep: fp32 W[k][n] -> fp16 [n][k] ---------------- */
__global__ void k_wprep(const float* __restrict__ W1a, const float* __restrict__ W1b) {
    int idx = blockIdx.x * blockDim.x + threadIdx.x;
    if (idx >= 2 * NPAD * FH) return;
    int branch = idx / (NPAD * FH);
    int rem = idx - branch * NPAD * FH;
    int n = rem / FH, k = rem - n * FH;
    const float* W = branch ? W1b : W1a;
    float w = (n < HID) ? W[k * HID + n] : 0.f;
    g_Wf[idx] = __float2half_rn(w);
}

/* ---------------- mma.sync fp16 GEMM v4: H = x(:,768 slice) @ W1 ----------------
 * CTA = 512 threads, 16 warps as 8(M) x 2(N); warp tile 16 x 104 (1 x 13 m16n8).
 * CTA tile M=128, N=208, BK=64 (12 iterations), double-buffered.
 * A: fp32 -> registers -> fp16 SMEM (128B rows + 16B pad, ldmatrix x4).
 * B: pre-converted fp16 streamed via cp.async.
 */
#define A_STB 144                  /* 64 fp16 = 128B + 16 pad */
#define B_STB 144
#define ASZ4  (128 * A_STB)        /* 18432 */
#define BSZ4  (NPAD * B_STB)       /* 29952 */
#define OFF_A4(s) ((s) * ASZ4)
#define OFF_B4(s) (2 * ASZ4 + (s) * BSZ4)
#define GEMM_SMEM (2 * ASZ4 + 2 * BSZ4)   /* 96768 B */

__global__ void __launch_bounds__(512) k_gemm_mma(const float* __restrict__ x) {
    extern __shared__ char smem[];
    const uint32_t sb = smem_u32(smem);
    const int tid  = threadIdx.x;
    const int wid  = tid >> 5, lane = tid & 31;
    const int wm   = wid >> 1;            /* 0..7: 16-row sub-tile */
    const int wn   = wid & 1;             /* 0..1: 104-col sub-tile */
    const int branch = blockIdx.y;
    const int row0 = blockIdx.x * 128;

    const __half* __restrict__ Wf = g_Wf + (size_t)branch * NPAD * FH;
    const float* __restrict__ xb = x + (size_t)branch * FH;

    float acc[13][4];
#pragma unroll
    for (int j = 0; j < 13; ++j)
#pragma unroll
        for (int q = 0; q < 4; ++q) acc[j][q] = 0.f;

    /* A loader: 4 threads per row, 16 fp32 each */
    const int a_row = tid >> 2;                 /* 0..127 */
    const int a_kof = (tid & 3) * 16;           /* fp32 k offset within 64 */
    const int a_rg  = row0 + a_row;
    const bool a_ok = (a_rg < N_NODES);
    const float* a_src_base = xb + (size_t)a_rg * FEAT + a_kof;
    const uint32_t a_smem_byte = a_row * A_STB + a_kof * 2;

    auto issue_B = [&](int kb, int s) {
        /* 208 rows x 8 chunks = 1664; 512 threads -> <=4 each */
#pragma unroll
        for (int it = 0; it < 4; ++it) {
            int idx = tid + it * 512;
            if (idx < NPAD * 8) {
                int n = idx >> 3, c = idx & 7;
                cp_async16(sb + OFF_B4(s) + n * B_STB + c * 16,
                           (const char*)(Wf + (size_t)n * FH + kb) + c * 16);
            }
        }
        CP_COMMIT();
    };

    auto store_A = [&](const float4* v, int s) {
        char* ap = smem + OFF_A4(s) + a_smem_byte;
        uint4 u0, u1;
        {
            __half2 h0 = __floats2half2_rn(v[0].x, v[0].y);
            __half2 h1 = __floats2half2_rn(v[0].z, v[0].w);
            __half2 h2 = __floats2half2_rn(v[1].x, v[1].y);
            __half2 h3 = __floats2half2_rn(v[1].z, v[1].w);
            u0 = make_uint4(*(uint32_t*)&h0, *(uint32_t*)&h1,
                            *(uint32_t*)&h2, *(uint32_t*)&h3);
            __half2 h4 = __floats2half2_rn(v[2].x, v[2].y);
            __half2 h5 = __floats2half2_rn(v[2].z, v[2].w);
            __half2 h6 = __floats2half2_rn(v[3].x, v[3].y);
            __half2 h7 = __floats2half2_rn(v[3].z, v[3].w);
            u1 = make_uint4(*(uint32_t*)&h4, *(uint32_t*)&h5,
                            *(uint32_t*)&h6, *(uint32_t*)&h7);
        }
        *(uint4*)(ap)      = u0;
        *(uint4*)(ap + 16) = u1;
    };

    /* ldsm lane mappings */
    const uint32_t a_ld_row = (lane & 7) + ((lane >> 3) & 1) * 8;
    const uint32_t a_ld_kb  = ((lane >> 4) & 1) * 16;
    const uint32_t ld4_row = (lane & 7) + ((lane >> 4) & 1) * 8;
    const uint32_t ld4_kb  = ((lane >> 3) & 1) * 16;
    const uint32_t ld2_row = lane & 7;
    const uint32_t ld2_kb  = ((lane >> 3) & 1) * 16;

    /* ---- prologue: stage 0 ---- */
    {
        float4 av[4];
#pragma unroll
        for (int i = 0; i < 4; ++i)
            av[i] = a_ok ? *(const float4*)(a_src_base + i * 4)
                         : make_float4(0.f, 0.f, 0.f, 0.f);
        issue_B(0, 0);
        store_A(av, 0);
        CP_WAIT0();
    }
    __syncthreads();

    for (int kb = 0; kb < 12; ++kb) {
        const int s = kb & 1;
        float4 av[4];
        const bool more = (kb < 11);
        if (more) {
#pragma unroll
            for (int i = 0; i < 4; ++i)
                av[i] = a_ok ? *(const float4*)(a_src_base + (kb + 1) * 64 + i * 4)
                             : make_float4(0.f, 0.f, 0.f, 0.f);
            issue_B((kb + 1) * 64, s ^ 1);
        }

        const uint32_t baseA = sb + OFF_A4(s);
        const uint32_t baseB = sb + OFF_B4(s);
#pragma unroll
        for (int ks = 0; ks < 4; ++ks) {
            uint32_t ah[4];
            {
                uint32_t r = wm * 16 + a_ld_row;
                uint32_t ab = r * A_STB + ks * 32 + a_ld_kb;
                ldsm_x4(baseA + ab, ah[0], ah[1], ah[2], ah[3]);
            }
#pragma unroll
            for (int ntp = 0; ntp < 6; ++ntp) {
                uint32_t n = wn * 104 + ntp * 16 + ld4_row;
                uint32_t bb = n * B_STB + ks * 32 + ld4_kb;
                uint32_t b0, b1, b2, b3;
                ldsm_x4(baseB + bb, b0, b1, b2, b3);
                mma_f16(acc[2 * ntp],     ah, b0, b1);
                mma_f16(acc[2 * ntp + 1], ah, b2, b3);
            }
            {
                uint32_t n = wn * 104 + 96 + ld2_row;
                uint32_t bb = n * B_STB + ks * 32 + ld2_kb;
                uint32_t b0, b1;
                ldsm_x2(baseB + bb, b0, b1);
                mma_f16(acc[12], ah, b0, b1);
            }
        }

        if (more) {
            store_A(av, s ^ 1);
            CP_WAIT0();
        }
        __syncthreads();
    }

    /* ---- epilogue: regs -> g_Hh (fp16) ---- */
    {
        int r0g = row0 + wm * 16 + (lane >> 2);
#pragma unroll
        for (int nt = 0; nt < 13; ++nt) {
            int col = wn * 104 + nt * 8 + (lane & 3) * 2;
            if (col < HID) {
                __half2 h01 = __floats2half2_rn(acc[nt][0], acc[nt][1]);
                __half2 h23 = __floats2half2_rn(acc[nt][2], acc[nt][3]);
                if (r0g < N_NODES)
                    *(__half2*)(g_Hh + (size_t)r0g * HB + branch * HID + col) = h01;
                if (r0g + 8 < N_NODES)
                    *(__half2*)(g_Hh + (size_t)(r0g + 8) * HB + branch * HID + col) = h23;
            }
        }
    }
}

/* ---------------- fused layer-1 SpMM + bias + relu + 200->2 ---------------- */
__device__ __forceinline__ void acc8(float* a, uint4 p, float w) {
    const __half2* h = (const __half2*)&p;
#pragma unroll
    for (int i = 0; i < 4; ++i) {
        float2 f = __half22float2(h[i]);
        a[2 * i]     += w * f.x;
        a[2 * i + 1] += w * f.y;
    }
}

__global__ void __launch_bounds__(256) k_spmm_fused(const float* __restrict__ b1a,
                                                    const float* __restrict__ b1b,
                                                    const float* __restrict__ W2a,
                                                    const float* __restrict__ W2b) {
    const int wid = threadIdx.x >> 5, lane = threadIdx.x & 31;
    const int n = blockIdx.x * 8 + wid;
    if (n >= N_NODES) return;

    float acc[16];
#pragma unroll
    for (int i = 0; i < 16; ++i) acc[i] = 0.f;

    const int e0 = g_off[n], e1 = g_off[n + 1];
    const uint4* __restrict__ Hq = (const uint4*)g_Hh;

    if (lane < 25) {
        const int base = lane * 2;
        int j = e0;
        for (; j + 1 < e1; j += 2) {
            uint2 ed0 = __ldg(&g_edge[j]);
            uint2 ed1 = __ldg(&g_edge[j + 1]);
            float w0 = __uint_as_float(ed0.y);
            float w1 = __uint_as_float(ed1.y);
            uint4 p0 = Hq[(size_t)ed0.x * 50 + base];
            uint4 q0 = Hq[(size_t)ed0.x * 50 + base + 1];
            uint4 p1 = Hq[(size_t)ed1.x * 50 + base];
            uint4 q1 = Hq[(size_t)ed1.x * 50 + base + 1];
            acc8(acc,     p0, w0);
            acc8(acc + 8, q0, w0);
            acc8(acc,     p1, w1);
            acc8(acc + 8, q1, w1);
        }
        if (j < e1) {
            uint2 ed0 = __ldg(&g_edge[j]);
            float w0 = __uint_as_float(ed0.y);
            uint4 p0 = Hq[(size_t)ed0.x * 50 + base];
            uint4 q0 = Hq[(size_t)ed0.x * 50 + base + 1];
            acc8(acc,     p0, w0);
            acc8(acc + 8, q0, w0);
        }
    }

    float za0 = 0.f, za1 = 0.f, zb0 = 0.f, zb1 = 0.f;
    if (lane < 25) {
#pragma unroll
        for (int c = 0; c < 16; ++c) {
            int col = lane * 16 + c;
            bool bB = (col >= HID);
            int hid = bB ? col - HID : col;
            float v = acc[c] + __ldg(bB ? &b1b[hid] : &b1a[hid]);
            v = fmaxf(v, 0.f);
            const float* __restrict__ W2 = bB ? W2b : W2a;
            float w0 = __ldg(&W2[hid * 2 + 0]);
            float w1 = __ldg(&W2[hid * 2 + 1]);
            if (bB) { zb0 += v * w0; zb1 += v * w1; }
            else    { za0 += v * w0; za1 += v * w1; }
        }
    }
#pragma unroll
    for (int o = 16; o; o >>= 1) {
        za0 += __shfl_xor_sync(0xffffffffu, za0, o);
        za1 += __shfl_xor_sync(0xffffffffu, za1, o);
        zb0 += __shfl_xor_sync(0xffffffffu, zb0, o);
        zb1 += __shfl_xor_sync(0xffffffffu, zb1, o);
    }
    if (lane == 0) {
        g_Z[n * 4 + 0] = za0;
        g_Z[n * 4 + 1] = za1;
        g_Z[n * 4 + 2] = zb0;
        g_Z[n * 4 + 3] = zb1;
    }
}

/* ---------------- layer-2 SpMM + softmax + vote ---------------- */
__global__ void __launch_bounds__(256) k_final(const float* __restrict__ b2a,
                                               const float* __restrict__ b2b,
                                               float* __restrict__ out) {
    int wid = threadIdx.x >> 5, lane = threadIdx.x & 31;
    int n = blockIdx.x * 8 + wid;
    if (n >= N_NODES) return;

    float s0 = 0.f, s1 = 0.f, s2 = 0.f, s3 = 0.f;
    int e0 = g_off[n], e1 = g_off[n + 1];
    const float4* __restrict__ Z4 = (const float4*)g_Z;
    for (int j = e0 + lane; j < e1; j += 32) {
        uint2 ed = __ldg(&g_edge[j]);
        float w  = __uint_as_float(ed.y);
        float4 z = Z4[ed.x];
        s0 += w * z.x;
        s1 += w * z.y;
        s2 += w * z.z;
        s3 += w * z.w;
    }
    for (int o = 16; o; o >>= 1) {
        s0 += __shfl_xor_sync(0xffffffffu, s0, o);
        s1 += __shfl_xor_sync(0xffffffffu, s1, o);
        s2 += __shfl_xor_sync(0xffffffffu, s2, o);
        s3 += __shfl_xor_sync(0xffffffffu, s3, o);
    }
    if (lane == 0) {
        float za0 = s0 + b2a[0], za1 = s1 + b2a[1];
        float m  = fmaxf(za0, za1);
        float ea0 = __expf(za0 - m), ea1 = __expf(za1 - m);
        float ia  = 1.f / (ea0 + ea1);
        float pa0 = ea0 * ia, pa1 = ea1 * ia;

        float zb0 = s2 + b2b[0], zb1 = s3 + b2b[1];
        m = fmaxf(zb0, zb1);
        float eb0 = __expf(zb0 - m), eb1 = __expf(zb1 - m);
        float ib  = 1.f / (eb0 + eb1);
        float pb0 = eb0 * ib, pb1 = eb1 * ib;

        float v0 = fmaxf(pa0, pb0), v1 = fmaxf(pa1, pb1);
        float inv = 1.f / (v0 + v1);
        out[n * 2 + 0] = v0 * inv;
        out[n * 2 + 1] = v1 * inv;
    }
}

/* ---------------- launch ---------------- */
extern "C" void kernel_launch(void* const* d_in, const int* in_sizes, int n_in,
                              void* d_out, int out_size) {
    const float* x    = (const float*)d_in[0];
    const int*   esrc = (const int*)  d_in[1];
    const int*   edst = (const int*)  d_in[2];
    const float* ew   = (const float*)d_in[3];
    const float* W1a  = (const float*)d_in[4];
    const float* b1a  = (const float*)d_in[5];
    const float* W2a  = (const float*)d_in[6];
    const float* b2a  = (const float*)d_in[7];
    const float* W1b  = (const float*)d_in[8];
    const float* b1b  = (const float*)d_in[9];
    const float* W2b  = (const float*)d_in[10];
    const float* b2b  = (const float*)d_in[11];
    float* out = (float*)d_out;

    void *p_deg = nullptr, *p_off = nullptr, *p_cursor = nullptr;
    cudaGetSymbolAddress(&p_deg, g_deg);
    cudaGetSymbolAddress(&p_off, g_off);
    cudaGetSymbolAddress(&p_cursor, g_cursor);

    cudaFuncSetAttribute(k_gemm_mma, cudaFuncAttributeMaxDynamicSharedMemorySize,
                         GEMM_SMEM);

    static cudaStream_t s2 = nullptr;
    static cudaEvent_t evF = nullptr, evJ = nullptr;
    if (!s2) {
        cudaStreamCreateWithFlags(&s2, cudaStreamNonBlocking);
        cudaEventCreateWithFlags(&evF, cudaEventDisableTiming);
        cudaEventCreateWithFlags(&evJ, cudaEventDisableTiming);
    }

    /* #1: weight prep (main) */
    k_wprep<<<(2 * NPAD * FH + 255) / 256, 256>>>(W1a, W1b);

    /* fork CSR onto s2 */
    cudaEventRecord(evF, 0);
    cudaStreamWaitEvent(s2, evF, 0);
    cudaMemsetAsync(p_deg, 0, N_NODES * sizeof(int), s2);
    k_count<<<(N_EDGES + 255) / 256, 256, 0, s2>>>(edst);
    k_scan_all<<<1, 1024, 0, s2>>>();

    /* #5: tensor-core layer-1 GEMM (main, both branches) */
    k_gemm_mma<<<dim3((N_NODES + 127) / 128, 2), 512, GEMM_SMEM>>>(x);

    cudaMemcpyAsync(p_cursor, p_off, N_NODES * sizeof(int),
                    cudaMemcpyDeviceToDevice, s2);
    k_fill<<<(N_EDGES + 255) / 256, 256, 0, s2>>>(esrc, edst, ew);
    cudaEventRecord(evJ, s2);

    /* join, then fused graph conv + hidden layer, layer-2 + vote */
    cudaStreamWaitEvent(0, evJ, 0);
    k_spmm_fused<<<(N_NODES + 7) / 8, 256>>>(b1a, b1b, W2a, W2b);
    k_final<<<(N_NODES + 7) / 8, 256>>>(b2a, b2b, out);
}